// round 15
// baseline (speedup 1.0000x reference)
#include <cuda_runtime.h>
#include <cuda_fp16.h>
#include <math.h>
#include <stdint.h>

#define HH 200
#define WW 352
#define HW 70400

// ---------------- static scratch ----------------
// channel-last fp16 planes: [img][HW][64]
__device__ __half g_x0s [4 * HW * 64];
__device__ __half g_x1s [4 * HW * 64];
__device__ __half g_aggs[4 * HW * 64];
__device__ __half g_hs  [HW * 64];
__device__ __half g_rhs [HW * 64];
__device__ float g_u   [HW * 64];              // update gate, channel-last
__device__ float g_hncl[4 * HW * 64];          // h_next, fp32 channel-last, per t
// fp16 weights: [g=c32*3+dy][dx][n][32ci]
__device__ __half g_wt_msg  [4 * 9 * 64  * 32];
__device__ __half g_wt_gates[6 * 9 * 128 * 32];
__device__ __half g_wt_can  [6 * 9 * 64  * 32];

// ---------------- helpers ----------------
__device__ __forceinline__ uint32_t smem_u32(const void* p) {
    uint32_t a;
    asm("{ .reg .u64 t; cvta.to.shared.u64 t, %1; cvt.u32.u64 %0, t; }" : "=r"(a) : "l"(p));
    return a;
}
__device__ __forceinline__ void cp16(uint32_t dst, const void* src) {
    asm volatile("cp.async.ca.shared.global [%0], [%1], 16;" :: "r"(dst), "l"(src));
}
__device__ __forceinline__ void cp_commit() {
    asm volatile("cp.async.commit_group;" ::: "memory");
}
template<int N_> __device__ __forceinline__ void cp_wait() {
    asm volatile("cp.async.wait_group %0;" :: "n"(N_) : "memory");
}
__device__ __forceinline__ void sts_zero16(uint32_t a) {
    asm volatile("st.shared.v4.b32 [%0], {%1,%1,%1,%1};" :: "r"(a), "r"(0u) : "memory");
}
__device__ __forceinline__ void ldsm_x4(uint32_t* r, uint32_t addr) {
    asm volatile("ldmatrix.sync.aligned.m8n8.x4.shared.b16 {%0,%1,%2,%3}, [%4];"
        : "=r"(r[0]), "=r"(r[1]), "=r"(r[2]), "=r"(r[3]) : "r"(addr));
}
__device__ __forceinline__ void mma16816(float* d, const uint32_t* a, const uint32_t* b) {
    asm volatile("mma.sync.aligned.m16n8k16.row.col.f32.f16.f16.f32 "
        "{%0,%1,%2,%3},{%4,%5,%6,%7},{%8,%9},{%0,%1,%2,%3};"
        : "+f"(d[0]), "+f"(d[1]), "+f"(d[2]), "+f"(d[3])
        : "r"(a[0]), "r"(a[1]), "r"(a[2]), "r"(a[3]), "r"(b[0]), "r"(b[1]));
}
__device__ __forceinline__ float fast_tanh(float v) {
    float e = __expf(2.f * v);
    return 1.f - 2.f / (e + 1.f);
}
__device__ __forceinline__ void store2(__half* hb, size_t off, float v0, float v1) {
    __half2 hp; hp.x = __float2half(v0); hp.y = __float2half(v1);
    *(__half2*)(hb + off) = hp;
}

// ---------------- weight prep (fp16) ----------------
__global__ void prep_w_k(const float* __restrict__ w, __half* __restrict__ wt,
                         int Cout, int Cin) {
    int total = (Cin / 32) * 9 * Cout * 32;
    for (int idx = blockIdx.x * blockDim.x + threadIdx.x; idx < total;
         idx += gridDim.x * blockDim.x) {
        int ci  = idx & 31;
        int n   = (idx >> 5) % Cout;
        int tap = (idx / (32 * Cout)) % 9;
        int c32 = idx / (32 * Cout * 9);
        int dy = tap / 3, dx = tap % 3;
        float v = w[(((size_t)n * Cin + c32 * 32 + ci) * 3 + dy) * 3 + dx];
        wt[(((size_t)(c32 * 3 + dy) * 3 + dx) * Cout + n) * 32 + ci] = __float2half(v);
    }
}

// ---------------- input prep: transpose to channel-last fp16 ----------------
__global__ __launch_bounds__(256) void prep_x_k(const float* __restrict__ x,
                                                __half* __restrict__ x0s,
                                                __half* __restrict__ x1s) {
    __shared__ float sf[64][132];
    const int tid = threadIdx.x;
    const int px0 = blockIdx.x * 128;
    const int img = blockIdx.y;
    const int ag  = blockIdx.z;
    const float* src = x + ((size_t)(ag * 4 + img) * 64) * HW;
    for (int i = tid; i < 64 * 128; i += 256) {
        int c = i >> 7, px = i & 127;
        sf[c][px] = src[(size_t)c * HW + px0 + px];
    }
    __syncthreads();
    __half* dst = (ag ? x1s : x0s) + (size_t)img * HW * 64;
    for (int i = tid; i < 128 * 8; i += 256) {
        int px = i >> 3, q = i & 7;
        __half hb[8];
#pragma unroll
        for (int j = 0; j < 8; j++)
            hb[j] = __float2half(sf[q * 8 + j][px]);
        *(uint4*)(dst + (size_t)(px0 + px) * 64 + q * 8) = *(const uint4*)hb;
    }
}

// ---------------- output transpose: channel-last fp32 -> NCHW fp32 ----------------
__global__ __launch_bounds__(256) void out_tr_k(const float* __restrict__ src,
                                                float* __restrict__ dst) {
    __shared__ float st[128][65];
    const int tid = threadIdx.x;
    const int px0 = blockIdx.x * 128;
    for (int i = tid; i < 128 * 64; i += 256) {
        int px = i >> 6, c = i & 63;       // c fastest -> coalesced src read
        st[px][c] = src[(size_t)(px0 + px) * 64 + c];
    }
    __syncthreads();
    for (int i = tid; i < 64 * 128; i += 256) {
        int c = i >> 7, px = i & 127;      // px fastest -> coalesced dst write
        dst[(size_t)c * HW + px0 + px] = st[px][c];
    }
}

// ---------------- fused implicit-GEMM conv (HMMA fp16 single-product) ----------------
struct Srcs { const __half* p[6]; };

// MODE 0 (msg, N=64):   agg = 0.5*(x0 + conv+b) -> fp16 (aggs); x0 from p[0] ch-last
// MODE 1 (gates,N=128): c<64: rhs = fp16(sigmoid * hs); c>=64: u = sigmoid (ch-last)
// MODE 2 (can,  N=64):  hn = (1-u)*hprev + u*tanh(conv+b) -> hncl (fp32 cl) + hs (fp16)
template<int MODE, int N>
__global__ __launch_bounds__(256, 2) void conv_mma_k(
    Srcs srcs, long long imgStride,
    const __half* __restrict__ wt,
    const float* __restrict__ bias,
    int nchunks,
    const __half* __restrict__ aux16,         // M1: hs (null at t=0)
    const float* __restrict__ uPlane,         // M2: u (ch-last)
    const float* __restrict__ hPrevF,         // M2: hncl[t-1] (null at t=0)
    __half* __restrict__ halfOut,             // M0: aggs(img); M1: rhs; M2: hs
    float* __restrict__ fpOut)                // M1: u; M2: hncl[t]
{
    extern __shared__ char dsm[];
    constexpr int MF  = 2;
    constexpr int NPW = N / 2;
    constexpr int NFP = NPW / 16;
    constexpr int NF  = NPW / 8;
    constexpr int A_BYTES = 3 * 130 * 80;              // 31,200
    constexpr int B_BYTES = 3 * N * 40 * 2;

    const int tid  = threadIdx.x;
    const int warp = tid >> 5, lane = tid & 31;
    const int xt = blockIdx.x, y = blockIdx.y, img = blockIdx.z;
    const int x0 = (xt < 2) ? xt * 128 : 224;

    char* base = (char*)(((uintptr_t)dsm + 127) & ~(uintptr_t)127);
    const uint32_t sA = smem_u32(base);
    const uint32_t sB = sA + A_BYTES;

    const int mbase = (warp & 3) * 32;
    const int nbase = (warp >> 2) * NPW;

    float acc[MF][NF][4];
#pragma unroll
    for (int i = 0; i < MF; i++)
#pragma unroll
        for (int j = 0; j < NF; j++)
#pragma unroll
            for (int q = 0; q < 4; q++) acc[i][j][q] = 0.f;

    const int a_row = lane & 15, a_col = (lane >> 4) * 8;
    const int b_n   = ((lane & 16) >> 1) + (lane & 7);
    const int b_k   = ((lane >> 3) & 1) * 8;

    const int G = nchunks * 3;

    auto stageA = [&](int chunk) {
        const __half* sp = srcs.p[chunk] + (size_t)img * imgStride;
        for (int idx = tid; idx < 3 * 130 * 4; idx += 256) {
            int quad = idx & 3;
            int px   = (idx >> 2) % 130;
            int r    = idx / 520;
            int gy = y - 1 + r, gx = x0 - 1 + px;
            uint32_t dst = sA + (uint32_t)((r * 130 + px) * 80 + quad * 16);
            if ((unsigned)gy < (unsigned)HH && (unsigned)gx < (unsigned)WW)
                cp16(dst, sp + (size_t)(gy * WW + gx) * 64 + quad * 8);
            else
                sts_zero16(dst);
        }
    };
    auto stageB = [&](int g, int bbuf) {
        const __half* ws = wt + (size_t)g * 3 * N * 32;
        uint32_t bb = sB + bbuf * B_BYTES;
        for (int idx = tid; idx < 3 * N * 4; idx += 256) {
            int quad = idx & 3;
            int n    = (idx >> 2) % N;
            int dx   = idx / (4 * N);
            cp16(bb + (uint32_t)((dx * N + n) * 80 + quad * 16),
                 ws + ((size_t)dx * N + n) * 32 + quad * 8);
        }
    };

    stageB(0, 0);
    cp_commit();

    for (int g = 0; g < G; g++) {
        const int chunk = g / 3, dy = g - chunk * 3;
        const int bbuf = g & 1;

        __syncthreads();
        if (dy == 0) { stageA(chunk); cp_commit(); }
        if (g + 1 < G) { stageB(g + 1, bbuf ^ 1); cp_commit(); }
        if (g + 1 < G) cp_wait<1>(); else cp_wait<0>();
        __syncthreads();

        const uint32_t bb = sB + bbuf * B_BYTES;
#pragma unroll
        for (int kt = 0; kt < 2; kt++) {
#pragma unroll
            for (int dx = 0; dx < 3; dx++) {
                uint32_t a[MF][4];
#pragma unroll
                for (int mf = 0; mf < MF; mf++) {
                    uint32_t addr = sA + (uint32_t)(((dy * 130 +
                        (mbase + mf * 16 + a_row + dx)) * 40 +
                        kt * 16 + a_col) * 2);
                    ldsm_x4(a[mf], addr);
                }
#pragma unroll
                for (int nfp = 0; nfp < NFP; nfp++) {
                    uint32_t t[4];
                    uint32_t addr = bb + (uint32_t)(((dx * N +
                        (nbase + nfp * 16 + b_n)) * 40 +
                        kt * 16 + b_k) * 2);
                    ldsm_x4(t, addr);
#pragma unroll
                    for (int half_ = 0; half_ < 2; half_++) {
                        uint32_t bfrag[2] = {t[half_ * 2], t[half_ * 2 + 1]};
                        int nf = nfp * 2 + half_;
#pragma unroll
                        for (int mf = 0; mf < MF; mf++)
                            mma16816(acc[mf][nf], a[mf], bfrag);
                    }
                }
            }
        }
    }

    // ---- epilogue (all channel-last, coalesced) ----
    const int gq = lane >> 2, q = lane & 3;
#pragma unroll
    for (int mf = 0; mf < MF; mf++) {
#pragma unroll
        for (int nf = 0; nf < NF; nf++) {
#pragma unroll
            for (int mh = 0; mh < 2; mh++) {
                int m  = mbase + mf * 16 + gq + mh * 8;
                int c0 = nbase + nf * 8 + q * 2;
                float v0 = acc[mf][nf][mh * 2 + 0] + bias[c0];
                float v1 = acc[mf][nf][mh * 2 + 1] + bias[c0 + 1];
                size_t pix = (size_t)y * WW + (x0 + m);
                size_t cl = pix * 64 + c0;
                if (MODE == 0) {
                    const __half* x0h = srcs.p[0] + (size_t)img * imgStride;
                    __half2 xp = *(const __half2*)(x0h + cl);
                    float a0 = 0.5f * (__half2float(xp.x) + v0);
                    float a1 = 0.5f * (__half2float(xp.y) + v1);
                    store2(halfOut + (size_t)img * HW * 64, cl, a0, a1);
                } else if (MODE == 1) {
                    float s0 = 1.f / (1.f + __expf(-v0));
                    float s1 = 1.f / (1.f + __expf(-v1));
                    if (c0 < 64) {
                        float h0 = 0.f, h1 = 0.f;
                        if (aux16) {
                            __half2 hp = *(const __half2*)(aux16 + cl);
                            h0 = __half2float(hp.x); h1 = __half2float(hp.y);
                        }
                        store2(halfOut, cl, s0 * h0, s1 * h1);
                    } else {
                        float2 up; up.x = s0; up.y = s1;
                        *(float2*)(fpOut + pix * 64 + (c0 - 64)) = up;
                    }
                } else {
                    float cn0 = fast_tanh(v0), cn1 = fast_tanh(v1);
                    float2 up = *(const float2*)(uPlane + cl);
                    float h0 = 0.f, h1 = 0.f;
                    if (hPrevF) {
                        float2 hp = *(const float2*)(hPrevF + cl);
                        h0 = hp.x; h1 = hp.y;
                    }
                    float hn0 = (1.f - up.x) * h0 + up.x * cn0;
                    float hn1 = (1.f - up.y) * h1 + up.y * cn1;
                    float2 hw; hw.x = hn0; hw.y = hn1;
                    *(float2*)(fpOut + cl) = hw;
                    store2(halfOut, cl, hn0, hn1);
                }
            }
        }
    }
}

// ---------------- host launcher ----------------
extern "C" void kernel_launch(void* const* d_in, const int* in_sizes, int n_in,
                              void* d_out, int out_size)
{
    const float* x       = (const float*)d_in[0];
    const float* msg_w   = (const float*)d_in[1];
    const float* msg_b   = (const float*)d_in[2];
    const float* gates_w = (const float*)d_in[3];
    const float* gates_b = (const float*)d_in[4];
    const float* can_w   = (const float*)d_in[5];
    const float* can_b   = (const float*)d_in[6];
    float* out = (float*)d_out;

    __half *x0s, *x1s, *aggs, *hs, *rhs, *wtm, *wtg, *wtc;
    float *u, *hncl;
    cudaGetSymbolAddress((void**)&x0s,  g_x0s);
    cudaGetSymbolAddress((void**)&x1s,  g_x1s);
    cudaGetSymbolAddress((void**)&aggs, g_aggs);
    cudaGetSymbolAddress((void**)&hs,   g_hs);
    cudaGetSymbolAddress((void**)&rhs,  g_rhs);
    cudaGetSymbolAddress((void**)&u,    g_u);
    cudaGetSymbolAddress((void**)&hncl, g_hncl);
    cudaGetSymbolAddress((void**)&wtm,  g_wt_msg);
    cudaGetSymbolAddress((void**)&wtg,  g_wt_gates);
    cudaGetSymbolAddress((void**)&wtc,  g_wt_can);

    static cudaStream_t sMsg = nullptr;
    static cudaEvent_t evP = nullptr, evT = nullptr;
    static cudaEvent_t evM[4] = {}, evC[4] = {};
    if (!sMsg) {
        cudaStreamCreateWithFlags(&sMsg, cudaStreamNonBlocking);
        cudaEventCreateWithFlags(&evP, cudaEventDisableTiming);
        cudaEventCreateWithFlags(&evT, cudaEventDisableTiming);
        for (int i = 0; i < 4; i++) {
            cudaEventCreateWithFlags(&evM[i], cudaEventDisableTiming);
            cudaEventCreateWithFlags(&evC[i], cudaEventDisableTiming);
        }
    }

    const int A_BYTES = 3 * 130 * 80;                           // 31,200
    const int smem64  = A_BYTES + 2 * (3 * 64 * 40 * 2) + 256;  // ~62.2KB
    const int smem128 = A_BYTES + 2 * (3 * 128 * 40 * 2) + 256; // ~92.9KB
    cudaFuncSetAttribute(conv_mma_k<0,64>,  cudaFuncAttributeMaxDynamicSharedMemorySize, smem64);
    cudaFuncSetAttribute(conv_mma_k<1,128>, cudaFuncAttributeMaxDynamicSharedMemorySize, smem128);
    cudaFuncSetAttribute(conv_mma_k<2,64>,  cudaFuncAttributeMaxDynamicSharedMemorySize, smem64);

    // ---- prep on main stream ----
    prep_w_k<<<128, 256>>>(msg_w,   wtm, 64,  128);
    prep_w_k<<<128, 256>>>(gates_w, wtg, 128, 192);
    prep_w_k<<<128, 256>>>(can_w,   wtc, 64,  192);
    prep_x_k<<<dim3(HW / 128, 4, 2), 256>>>(x, x0s, x1s);
    cudaEventRecord(evP, 0);

    const long long imgStrideHf = (long long)HW * 64;

    // ---- Phase A on msg stream ----
    cudaStreamWaitEvent(sMsg, evP, 0);
    for (int t = 0; t < 4; t++) {
        Srcs s{};
        s.p[0] = x0s + (size_t)t * imgStrideHf;
        s.p[1] = x0s + (size_t)t * imgStrideHf + 32;
        s.p[2] = x1s + (size_t)t * imgStrideHf;
        s.p[3] = x1s + (size_t)t * imgStrideHf + 32;
        conv_mma_k<0,64><<<dim3(3, HH, 1), 256, smem64, sMsg>>>(
            s, 0, wtm, msg_b, 4,
            nullptr, nullptr, nullptr,
            aggs + (size_t)t * imgStrideHf, nullptr);
        cudaEventRecord(evM[t], sMsg);
    }

    // ---- Phase B on main stream; out transposes on msg stream ----
    for (int t = 0; t < 4; t++) {
        cudaStreamWaitEvent(0, evM[t], 0);
        const __half* x0t = x0s  + (size_t)t * imgStrideHf;
        const __half* agt = aggs + (size_t)t * imgStrideHf;
        {
            Srcs s{};
            s.p[0] = x0t; s.p[1] = x0t + 32;
            s.p[2] = agt; s.p[3] = agt + 32;
            s.p[4] = hs;  s.p[5] = hs + 32;
            conv_mma_k<1,128><<<dim3(3, HH, 1), 256, smem128>>>(
                s, 0, wtg, gates_b, t ? 6 : 4,
                t ? hs : nullptr, nullptr, nullptr, rhs, u);
        }
        {
            Srcs s{};
            s.p[0] = x0t; s.p[1] = x0t + 32;
            s.p[2] = agt; s.p[3] = agt + 32;
            s.p[4] = rhs; s.p[5] = rhs + 32;
            conv_mma_k<2,64><<<dim3(3, HH, 1), 256, smem64>>>(
                s, 0, wtc, can_b, t ? 6 : 4,
                nullptr, u, t ? (hncl + (size_t)(t - 1) * HW * 64) : nullptr,
                hs, hncl + (size_t)t * HW * 64);
        }
        cudaEventRecord(evC[t], 0);
        cudaStreamWaitEvent(sMsg, evC[t], 0);
        out_tr_k<<<dim3(HW / 128), 256, 0, sMsg>>>(
            hncl + (size_t)t * HW * 64, out + (size_t)t * 64 * HW);
    }
    cudaEventRecord(evT, sMsg);
    cudaStreamWaitEvent(0, evT, 0);   // join fork for graph capture
}

// round 16
// speedup vs baseline: 1.1422x; 1.1422x over previous
#include <cuda_runtime.h>
#include <cuda_fp16.h>
#include <math.h>
#include <stdint.h>

#define HH 200
#define WW 352
#define HW 70400

// ---------------- static scratch ----------------
// channel-last fp16 planes: [img][HW][64]
__device__ __half g_x0s [4 * HW * 64];
__device__ __half g_x1s [4 * HW * 64];
__device__ __half g_aggs[4 * HW * 64];
__device__ __half g_hs  [HW * 64];
__device__ __half g_rhs [HW * 64];
__device__ float g_u[HW * 64];                 // update gate, channel-last
// fp16 weights: [g=c32*3+dy][dx][n][32ci]
__device__ __half g_wt_msg  [4 * 9 * 64  * 32];
__device__ __half g_wt_gates[6 * 9 * 128 * 32];
__device__ __half g_wt_can  [6 * 9 * 64  * 32];

// ---------------- helpers ----------------
__device__ __forceinline__ uint32_t smem_u32(const void* p) {
    uint32_t a;
    asm("{ .reg .u64 t; cvta.to.shared.u64 t, %1; cvt.u32.u64 %0, t; }" : "=r"(a) : "l"(p));
    return a;
}
__device__ __forceinline__ void cp16(uint32_t dst, const void* src) {
    asm volatile("cp.async.ca.shared.global [%0], [%1], 16;" :: "r"(dst), "l"(src));
}
__device__ __forceinline__ void cp_commit() {
    asm volatile("cp.async.commit_group;" ::: "memory");
}
template<int N_> __device__ __forceinline__ void cp_wait() {
    asm volatile("cp.async.wait_group %0;" :: "n"(N_) : "memory");
}
__device__ __forceinline__ void sts_zero16(uint32_t a) {
    asm volatile("st.shared.v4.b32 [%0], {%1,%1,%1,%1};" :: "r"(a), "r"(0u) : "memory");
}
__device__ __forceinline__ void ldsm_x4(uint32_t* r, uint32_t addr) {
    asm volatile("ldmatrix.sync.aligned.m8n8.x4.shared.b16 {%0,%1,%2,%3}, [%4];"
        : "=r"(r[0]), "=r"(r[1]), "=r"(r[2]), "=r"(r[3]) : "r"(addr));
}
__device__ __forceinline__ void mma16816(float* d, const uint32_t* a, const uint32_t* b) {
    asm volatile("mma.sync.aligned.m16n8k16.row.col.f32.f16.f16.f32 "
        "{%0,%1,%2,%3},{%4,%5,%6,%7},{%8,%9},{%0,%1,%2,%3};"
        : "+f"(d[0]), "+f"(d[1]), "+f"(d[2]), "+f"(d[3])
        : "r"(a[0]), "r"(a[1]), "r"(a[2]), "r"(a[3]), "r"(b[0]), "r"(b[1]));
}
__device__ __forceinline__ float fast_tanh(float v) {
    float e = __expf(2.f * v);
    return 1.f - 2.f / (e + 1.f);
}
__device__ __forceinline__ void store2(__half* hb, size_t off, float v0, float v1) {
    __half2 hp; hp.x = __float2half(v0); hp.y = __float2half(v1);
    *(__half2*)(hb + off) = hp;
}

// ---------------- weight prep (fp16) ----------------
__global__ void prep_w_k(const float* __restrict__ w, __half* __restrict__ wt,
                         int Cout, int Cin) {
    int total = (Cin / 32) * 9 * Cout * 32;
    for (int idx = blockIdx.x * blockDim.x + threadIdx.x; idx < total;
         idx += gridDim.x * blockDim.x) {
        int ci  = idx & 31;
        int n   = (idx >> 5) % Cout;
        int tap = (idx / (32 * Cout)) % 9;
        int c32 = idx / (32 * Cout * 9);
        int dy = tap / 3, dx = tap % 3;
        float v = w[(((size_t)n * Cin + c32 * 32 + ci) * 3 + dy) * 3 + dx];
        wt[(((size_t)(c32 * 3 + dy) * 3 + dx) * Cout + n) * 32 + ci] = __float2half(v);
    }
}

// ---------------- input prep: transpose to channel-last fp16 ----------------
__global__ __launch_bounds__(256) void prep_x_k(const float* __restrict__ x,
                                                __half* __restrict__ x0s,
                                                __half* __restrict__ x1s) {
    __shared__ float sf[64][132];
    const int tid = threadIdx.x;
    const int px0 = blockIdx.x * 128;
    const int img = blockIdx.y;
    const int ag  = blockIdx.z;
    const float* src = x + ((size_t)(ag * 4 + img) * 64) * HW;
    for (int i = tid; i < 64 * 128; i += 256) {
        int c = i >> 7, px = i & 127;
        sf[c][px] = src[(size_t)c * HW + px0 + px];
    }
    __syncthreads();
    __half* dst = (ag ? x1s : x0s) + (size_t)img * HW * 64;
    for (int i = tid; i < 128 * 8; i += 256) {
        int px = i >> 3, q = i & 7;
        __half hb[8];
#pragma unroll
        for (int j = 0; j < 8; j++)
            hb[j] = __float2half(sf[q * 8 + j][px]);
        *(uint4*)(dst + (size_t)(px0 + px) * 64 + q * 8) = *(const uint4*)hb;
    }
}

// ---------------- fused implicit-GEMM conv (512-thread multi-row CTA) ----------------
struct Srcs { const __half* p[6]; };

// ROWS output rows per CTA (M = 128*ROWS). 16 warps: WM = M/64, WN = 16/WM.
// MODE 0 (msg, N=64,  ROWS=4): agg = 0.5*(x0 + conv+b) -> fp16 (aggs)
// MODE 1 (gates,N=128,ROWS=2): c<64: rhs = fp16(sigmoid*h); c>=64: u = sigmoid (cl)
// MODE 2 (can, N=64,  ROWS=4): hn = (1-u)*h + u*tanh(conv+b) -> fp32 NCHW + fp16 (hs)
template<int MODE, int N, int ROWS>
__global__ __launch_bounds__(512, 1) void conv_mma_k(
    Srcs srcs,
    const __half* __restrict__ wt,
    const float* __restrict__ bias,
    int nchunks,
    const float* __restrict__ fpA,            // M0: x0 fp32 NCHW; M1/M2: h fp32 NCHW
    const float* __restrict__ fpB,            // M2: u (channel-last)
    __half* __restrict__ halfOut,             // M0: aggs(img); M1: rhs; M2: hs
    float* __restrict__ fpOut)                // M1: u (cl); M2: d_out slice
{
    extern __shared__ char dsm[];
    constexpr int WM = (128 * ROWS) / 64;              // 8 (ROWS=4) or 4 (ROWS=2)
    constexpr int MF = 4;                              // 4 m-frags of 16 per warp
    constexpr int NF = 4;                              // 32 n per warp
    constexpr int NFP = 2;
    constexpr int AR = ROWS + 2;
    constexpr int A_BYTES = AR * 130 * 80;
    constexpr int B_BYTES = 3 * N * 40 * 2;

    const int tid  = threadIdx.x;
    const int warp = tid >> 5, lane = tid & 31;
    const int xt = blockIdx.x, by = blockIdx.y, img = blockIdx.z;
    const int x0 = (xt < 2) ? xt * 128 : 224;
    const int y0 = by * ROWS;

    char* base = (char*)(((uintptr_t)dsm + 127) & ~(uintptr_t)127);
    const uint32_t sA = smem_u32(base);
    const uint32_t sB = sA + A_BYTES;

    const int mbase = (warp % WM) * 64;
    const int nbase = (warp / WM) * 32;

    float acc[MF][NF][4];
#pragma unroll
    for (int i = 0; i < MF; i++)
#pragma unroll
        for (int j = 0; j < NF; j++)
#pragma unroll
            for (int q = 0; q < 4; q++) acc[i][j][q] = 0.f;

    const int a_row = lane & 15, a_col = (lane >> 4) * 8;
    const int b_n   = ((lane & 16) >> 1) + (lane & 7);
    const int b_k   = ((lane >> 3) & 1) * 8;

    const int G = nchunks * 3;

    auto stageA = [&](int chunk) {
        const __half* sp = srcs.p[chunk];
        for (int idx = tid; idx < AR * 130 * 4; idx += 512) {
            int quad = idx & 3;
            int px   = (idx >> 2) % 130;
            int r    = idx / 520;
            int gy = y0 - 1 + r, gx = x0 - 1 + px;
            uint32_t dst = sA + (uint32_t)((r * 130 + px) * 80 + quad * 16);
            if ((unsigned)gy < (unsigned)HH && (unsigned)gx < (unsigned)WW)
                cp16(dst, sp + (size_t)(gy * WW + gx) * 64 + quad * 8);
            else
                sts_zero16(dst);
        }
    };
    auto stageB = [&](int g, int bbuf) {
        const __half* ws = wt + (size_t)g * 3 * N * 32;
        uint32_t bb = sB + bbuf * B_BYTES;
        for (int idx = tid; idx < 3 * N * 4; idx += 512) {
            int quad = idx & 3;
            int n    = (idx >> 2) % N;
            int dx   = idx / (4 * N);
            cp16(bb + (uint32_t)((dx * N + n) * 80 + quad * 16),
                 ws + ((size_t)dx * N + n) * 32 + quad * 8);
        }
    };

    stageB(0, 0);
    cp_commit();

    for (int g = 0; g < G; g++) {
        const int chunk = g / 3, dy = g - chunk * 3;
        const int bbuf = g & 1;

        __syncthreads();                      // prior compute done with A + B[bbuf^1]
        if (dy == 0) { stageA(chunk); cp_commit(); }
        if (g + 1 < G) { stageB(g + 1, bbuf ^ 1); cp_commit(); }
        if (g + 1 < G) cp_wait<1>(); else cp_wait<0>();
        __syncthreads();

        const uint32_t bb = sB + bbuf * B_BYTES;
#pragma unroll
        for (int kt = 0; kt < 2; kt++) {
#pragma unroll
            for (int dx = 0; dx < 3; dx++) {
                uint32_t a[MF][4];
#pragma unroll
                for (int mf = 0; mf < MF; mf++) {
                    int mb   = mbase + mf * 16;
                    int rOut = mb >> 7;               // output row within CTA
                    int pxb  = mb & 127;
                    uint32_t addr = sA + (uint32_t)((((rOut + dy) * 130 +
                        (pxb + a_row + dx)) * 40 + kt * 16 + a_col) * 2);
                    ldsm_x4(a[mf], addr);
                }
#pragma unroll
                for (int nfp = 0; nfp < NFP; nfp++) {
                    uint32_t t[4];
                    uint32_t addr = bb + (uint32_t)(((dx * N +
                        (nbase + nfp * 16 + b_n)) * 40 +
                        kt * 16 + b_k) * 2);
                    ldsm_x4(t, addr);
#pragma unroll
                    for (int half_ = 0; half_ < 2; half_++) {
                        uint32_t bfrag[2] = {t[half_ * 2], t[half_ * 2 + 1]};
                        int nf = nfp * 2 + half_;
#pragma unroll
                        for (int mf = 0; mf < MF; mf++)
                            mma16816(acc[mf][nf], a[mf], bfrag);
                    }
                }
            }
        }
    }

    // ---- epilogue (R14 semantics) ----
    const int gq = lane >> 2, q = lane & 3;
#pragma unroll
    for (int mf = 0; mf < MF; mf++) {
#pragma unroll
        for (int nf = 0; nf < NF; nf++) {
#pragma unroll
            for (int mh = 0; mh < 2; mh++) {
                int m  = mbase + mf * 16 + gq + mh * 8;
                int c0 = nbase + nf * 8 + q * 2;
                float v0 = acc[mf][nf][mh * 2 + 0] + bias[c0];
                float v1 = acc[mf][nf][mh * 2 + 1] + bias[c0 + 1];
                int rOut = m >> 7, px = m & 127;
                size_t pix = (size_t)(y0 + rOut) * WW + (x0 + px);
                size_t o0 = (size_t)c0 * HW + pix;
                size_t o1 = o0 + HW;
                if (MODE == 0) {
                    float a0 = 0.5f * (fpA[o0] + v0);
                    float a1 = 0.5f * (fpA[o1] + v1);
                    store2(halfOut, pix * 64 + c0, a0, a1);
                } else if (MODE == 1) {
                    float s0 = 1.f / (1.f + __expf(-v0));
                    float s1 = 1.f / (1.f + __expf(-v1));
                    if (c0 < 64) {
                        float h0 = fpA ? fpA[o0] : 0.f;
                        float h1 = fpA ? fpA[o1] : 0.f;
                        store2(halfOut, pix * 64 + c0, s0 * h0, s1 * h1);
                    } else {
                        float2 up; up.x = s0; up.y = s1;
                        *(float2*)(fpOut + pix * 64 + (c0 - 64)) = up;
                    }
                } else {
                    float cn0 = fast_tanh(v0), cn1 = fast_tanh(v1);
                    float2 up = *(const float2*)(fpB + pix * 64 + c0);
                    float h0 = fpA ? fpA[o0] : 0.f;
                    float h1 = fpA ? fpA[o1] : 0.f;
                    float hn0 = (1.f - up.x) * h0 + up.x * cn0;
                    float hn1 = (1.f - up.y) * h1 + up.y * cn1;
                    fpOut[o0] = hn0;
                    fpOut[o1] = hn1;
                    store2(halfOut, pix * 64 + c0, hn0, hn1);
                }
            }
        }
    }
}

// ---------------- host launcher ----------------
extern "C" void kernel_launch(void* const* d_in, const int* in_sizes, int n_in,
                              void* d_out, int out_size)
{
    const float* x       = (const float*)d_in[0];
    const float* msg_w   = (const float*)d_in[1];
    const float* msg_b   = (const float*)d_in[2];
    const float* gates_w = (const float*)d_in[3];
    const float* gates_b = (const float*)d_in[4];
    const float* can_w   = (const float*)d_in[5];
    const float* can_b   = (const float*)d_in[6];
    float* out = (float*)d_out;

    __half *x0s, *x1s, *aggs, *hs, *rhs, *wtm, *wtg, *wtc;
    float* u;
    cudaGetSymbolAddress((void**)&x0s,  g_x0s);
    cudaGetSymbolAddress((void**)&x1s,  g_x1s);
    cudaGetSymbolAddress((void**)&aggs, g_aggs);
    cudaGetSymbolAddress((void**)&hs,   g_hs);
    cudaGetSymbolAddress((void**)&rhs,  g_rhs);
    cudaGetSymbolAddress((void**)&u,    g_u);
    cudaGetSymbolAddress((void**)&wtm,  g_wt_msg);
    cudaGetSymbolAddress((void**)&wtg,  g_wt_gates);
    cudaGetSymbolAddress((void**)&wtc,  g_wt_can);

    static cudaStream_t sMsg = nullptr;
    static cudaEvent_t evP = nullptr;
    static cudaEvent_t evM[4] = {};
    if (!sMsg) {
        cudaStreamCreateWithFlags(&sMsg, cudaStreamNonBlocking);
        cudaEventCreateWithFlags(&evP, cudaEventDisableTiming);
        for (int i = 0; i < 4; i++)
            cudaEventCreateWithFlags(&evM[i], cudaEventDisableTiming);
    }

    const int smem64  = 6 * 130 * 80 + 2 * (3 * 64 * 40 * 2) + 256;   // ~93.4KB
    const int smem128 = 4 * 130 * 80 + 2 * (3 * 128 * 40 * 2) + 256;  // ~103.3KB
    cudaFuncSetAttribute((const void*)conv_mma_k<0,64,4>,
                         cudaFuncAttributeMaxDynamicSharedMemorySize, smem64);
    cudaFuncSetAttribute((const void*)conv_mma_k<1,128,2>,
                         cudaFuncAttributeMaxDynamicSharedMemorySize, smem128);
    cudaFuncSetAttribute((const void*)conv_mma_k<2,64,4>,
                         cudaFuncAttributeMaxDynamicSharedMemorySize, smem64);

    // ---- prep on main stream ----
    prep_w_k<<<128, 256>>>(msg_w,   wtm, 64,  128);
    prep_w_k<<<128, 256>>>(gates_w, wtg, 128, 192);
    prep_w_k<<<128, 256>>>(can_w,   wtc, 64,  192);
    prep_x_k<<<dim3(HW / 128, 4, 2), 256>>>(x, x0s, x1s);
    cudaEventRecord(evP, 0);

    const size_t imgHf = (size_t)HW * 64;

    // ---- Phase A on msg stream: one launch per image ----
    cudaStreamWaitEvent(sMsg, evP, 0);
    for (int t = 0; t < 4; t++) {
        Srcs s{};
        s.p[0] = x0s + t * imgHf;
        s.p[1] = x0s + t * imgHf + 32;
        s.p[2] = x1s + t * imgHf;
        s.p[3] = x1s + t * imgHf + 32;
        conv_mma_k<0,64,4><<<dim3(3, HH / 4, 1), 512, smem64, sMsg>>>(
            s, wtm, msg_b, 4,
            x + (size_t)t * 64 * HW, nullptr,
            aggs + t * imgHf, nullptr);
        cudaEventRecord(evM[t], sMsg);
    }

    // ---- Phase B on main stream ----
    for (int t = 0; t < 4; t++) {
        cudaStreamWaitEvent(0, evM[t], 0);
        const __half* x0t = x0s  + t * imgHf;
        const __half* agt = aggs + t * imgHf;
        const float* hp = t ? (out + (size_t)(t - 1) * 64 * HW) : nullptr;
        {
            Srcs s{};
            s.p[0] = x0t; s.p[1] = x0t + 32;
            s.p[2] = agt; s.p[3] = agt + 32;
            s.p[4] = hs;  s.p[5] = hs + 32;
            conv_mma_k<1,128,2><<<dim3(3, HH / 2, 1), 512, smem128>>>(
                s, wtg, gates_b, t ? 6 : 4, hp, nullptr, rhs, u);
        }
        {
            Srcs s{};
            s.p[0] = x0t; s.p[1] = x0t + 32;
            s.p[2] = agt; s.p[3] = agt + 32;
            s.p[4] = rhs; s.p[5] = rhs + 32;
            conv_mma_k<2,64,4><<<dim3(3, HH / 4, 1), 512, smem64>>>(
                s, wtc, can_b, t ? 6 : 4, hp, u, hs, out + (size_t)t * 64 * HW);
        }
    }
}